// round 1
// baseline (speedup 1.0000x reference)
#include <cuda_runtime.h>
#include <math_constants.h>

// Problem constants
#define NN 8192
#define CC 256
#define TM 128          // rows of sim tile per block
#define TN 128          // cols of sim tile per block
#define KC 32           // k-chunk per smem stage
#define NSPLIT 16       // column splits (partial LSE per split)
#define CPS (NN / NSPLIT)   // 512 cols per block
#define NCT (CPS / TN)      // 4 col tiles per block
#define INV_T 14.285714285714285714f   // 1/0.07
#define L2E 1.4426950408889634f

typedef unsigned long long u64;

// Scratch (device globals; no allocations allowed)
__device__ float g_pm[NN * NSPLIT];
__device__ float g_ps[NN * NSPLIT];
__device__ float g_pos[NN];

__device__ __forceinline__ void ffma2(u64 &d, u64 a, u64 b) {
    // packed fp32x2 FMA (Blackwell): d.lo += a.lo*b.lo; d.hi += a.hi*b.hi
    asm("fma.rn.f32x2 %0, %1, %2, %0;" : "+l"(d) : "l"(a), "l"(b));
}

struct SmTile {
    float2 Qs[KC / 2][TM + 1];   // [16][129] float2, +1 pad kills fill-store conflicts
    float2 Ks[KC / 2][TN + 1];
};
struct SmRed {
    float m[TM][16];
    float s[TM][16];
};

// ---------------------------------------------------------------------------
// Main kernel: per (rowBlock, split), compute partial (max, sumexp) of
// sim[row, colRange]/T where sim = q @ k^T. LSE is permutation-invariant in
// columns, so thread->element maps are chosen purely for conflict-free LDS.
// ---------------------------------------------------------------------------
__global__ __launch_bounds__(256, 1)
void sim_lse_kernel(const float* __restrict__ q, const float* __restrict__ k) {
    __shared__ union { SmTile t; SmRed r; } sm;

    const int tid = threadIdx.x;
    const int tx = tid & 15;         // col group
    const int ty = tid >> 4;         // row group
    const int split = blockIdx.x;
    const int rowBase = blockIdx.y * TM;

    // running per-row (max, sumexp) for the 8 rows this thread owns:
    // local rows r = ty + 16*i
    float rm[8], rs[8];
#pragma unroll
    for (int i = 0; i < 8; i++) { rm[i] = -CUDART_INF_F; rs[i] = 0.0f; }

    for (int ct = 0; ct < NCT; ct++) {
        const int colBase = split * CPS + ct * TN;

        u64 acc[8][8];
#pragma unroll
        for (int i = 0; i < 8; i++)
#pragma unroll
            for (int j = 0; j < 8; j++) acc[i][j] = 0ull;

        for (int kc = 0; kc < CC; kc += KC) {
            __syncthreads();   // previous compute finished reading smem
            // ---- fill: 128 rows x 32 k for both Q-tile and K-tile ----
            // f indexes 1024 float4 loads; r = f>>3 row, g = f&7 k-group.
            // Lanes within a warp share r in groups of 8 -> 128B coalesced.
#pragma unroll
            for (int it = 0; it < 4; it++) {
                const int f = tid + it * 256;
                const int r = f >> 3;
                const int g = f & 7;
                const float4 v = *(const float4*)(q + (size_t)(rowBase + r) * CC + kc + g * 4);
                sm.t.Qs[g * 2 + 0][r] = make_float2(v.x, v.y);
                sm.t.Qs[g * 2 + 1][r] = make_float2(v.z, v.w);
                const float4 w = *(const float4*)(k + (size_t)(colBase + r) * CC + kc + g * 4);
                sm.t.Ks[g * 2 + 0][r] = make_float2(w.x, w.y);
                sm.t.Ks[g * 2 + 1][r] = make_float2(w.z, w.w);
            }
            __syncthreads();

            // ---- compute: 16 packed-k steps, 8x8 register tile ----
#pragma unroll
            for (int p = 0; p < KC / 2; p++) {
                u64 a[8], b[8];
#pragma unroll
                for (int i = 0; i < 8; i++)
                    a[i] = *(const u64*)&sm.t.Qs[p][ty + 16 * i];
#pragma unroll
                for (int j = 0; j < 8; j++)
                    b[j] = *(const u64*)&sm.t.Ks[p][tx + 16 * j];
#pragma unroll
                for (int i = 0; i < 8; i++)
#pragma unroll
                    for (int j = 0; j < 8; j++)
                        ffma2(acc[i][j], a[i], b[j]);
            }
        }

        // ---- online LSE update over this 8x8 block of columns ----
#pragma unroll
        for (int i = 0; i < 8; i++) {
            float x[8];
            float mloc = -CUDART_INF_F;
#pragma unroll
            for (int j = 0; j < 8; j++) {
                const float2 v = *reinterpret_cast<const float2*>(&acc[i][j]);
                x[j] = (v.x + v.y) * INV_T;
                mloc = fmaxf(mloc, x[j]);
            }
            const float mn = fmaxf(rm[i], mloc);
            float snew = rs[i] * exp2f((rm[i] - mn) * L2E);
#pragma unroll
            for (int j = 0; j < 8; j++)
                snew += exp2f((x[j] - mn) * L2E);
            rm[i] = mn;
            rs[i] = snew;
        }
    }

    // ---- reduce 16 tx-partials per row, write split partials ----
    __syncthreads();
#pragma unroll
    for (int i = 0; i < 8; i++) {
        const int r = ty + 16 * i;
        sm.r.m[r][tx] = rm[i];
        sm.r.s[r][tx] = rs[i];
    }
    __syncthreads();
    if (tid < TM) {
        float mg = -CUDART_INF_F;
#pragma unroll
        for (int t = 0; t < 16; t++) mg = fmaxf(mg, sm.r.m[tid][t]);
        float sg = 0.0f;
#pragma unroll
        for (int t = 0; t < 16; t++)
            sg += sm.r.s[tid][t] * exp2f((sm.r.m[tid][t] - mg) * L2E);
        const int row = rowBase + tid;
        g_pm[row * NSPLIT + split] = mg;
        g_ps[row * NSPLIT + split] = sg;
    }
}

// ---------------------------------------------------------------------------
// Diagonal: pos[i] = (q_i . k_i) / T, one warp per row
// ---------------------------------------------------------------------------
__global__ void pos_kernel(const float* __restrict__ q, const float* __restrict__ k) {
    const int warp = (blockIdx.x * blockDim.x + threadIdx.x) >> 5;
    const int lane = threadIdx.x & 31;
    if (warp >= NN) return;
    const float4* q4 = (const float4*)(q + (size_t)warp * CC);
    const float4* k4 = (const float4*)(k + (size_t)warp * CC);
    float s = 0.0f;
#pragma unroll
    for (int t = 0; t < 2; t++) {
        const float4 a = q4[lane + 32 * t];
        const float4 b = k4[lane + 32 * t];
        s += a.x * b.x + a.y * b.y + a.z * b.z + a.w * b.w;
    }
#pragma unroll
    for (int off = 16; off; off >>= 1)
        s += __shfl_xor_sync(0xFFFFFFFFu, s, off);
    if (lane == 0) g_pos[warp] = s * INV_T;
}

// ---------------------------------------------------------------------------
// Combine: merge split partials per row, mean(lse - pos). Single block,
// fixed reduction order -> deterministic.
// ---------------------------------------------------------------------------
__global__ void combine_kernel(float* __restrict__ out) {
    __shared__ float red[256];
    float tot = 0.0f;
    for (int r = threadIdx.x; r < NN; r += 256) {
        const float* pm = g_pm + r * NSPLIT;
        const float* ps = g_ps + r * NSPLIT;
        float mg = -CUDART_INF_F;
#pragma unroll
        for (int p = 0; p < NSPLIT; p++) mg = fmaxf(mg, pm[p]);
        float sg = 0.0f;
#pragma unroll
        for (int p = 0; p < NSPLIT; p++)
            sg += ps[p] * exp2f((pm[p] - mg) * L2E);
        tot += mg + logf(sg) - g_pos[r];
    }
    red[threadIdx.x] = tot;
    __syncthreads();
    for (int o = 128; o; o >>= 1) {
        if (threadIdx.x < o) red[threadIdx.x] += red[threadIdx.x + o];
        __syncthreads();
    }
    if (threadIdx.x == 0) out[0] = red[0] / (float)NN;
}

extern "C" void kernel_launch(void* const* d_in, const int* in_sizes, int n_in,
                              void* d_out, int out_size) {
    const float* q = (const float*)d_in[0];
    const float* k = (const float*)d_in[1];
    float* out = (float*)d_out;

    pos_kernel<<<NN / 8, 256>>>(q, k);
    dim3 grid(NSPLIT, NN / TM);
    sim_lse_kernel<<<grid, 256>>>(q, k);
    combine_kernel<<<1, 256>>>(out);
}

// round 3
// speedup vs baseline: 5.4887x; 5.4887x over previous
#include <cuda_runtime.h>
#include <cuda_fp16.h>
#include <math_constants.h>

// ---------------------------------------------------------------------------
// Problem constants
// ---------------------------------------------------------------------------
#define NN 8192
#define CC 256
#define TM 128                  // CTA rows
#define TNT 256                 // CTA col-tile width
#define NSPLIT 2
#define CPS (NN / NSPLIT)       // 4096 cols per CTA
#define NTILE (CPS / TNT)       // 16 col tiles
#define KCH 64                  // k per chunk
#define NCHUNKS (NTILE * 4)     // 64 chunk steps (4 chunks of 64 = K 256 per tile)
#define INV_T 14.285714285714285714f
#define L2E 1.4426950408889634f

// SMEM layout (dynamic)
#define A_STRIDE 528            // 256 halves + 8 pad = 528 B per row
#define B_STRIDE 144            // 64 halves + 8 pad = 144 B per row
#define SA 0
#define SA_BYTES (TM * A_STRIDE)            // 67584
#define SB (SA + SA_BYTES)
#define SB_STAGE (TNT * B_STRIDE)           // 36864
#define SRED_M (SB + 2 * SB_STAGE)          // 141312
#define SRED_S (SRED_M + TM * 4 * 4)        // +2048
#define SM_TOTAL (SRED_S + TM * 4 * 4)      // 145408

typedef unsigned int u32;
typedef unsigned long long u64;

// ---------------------------------------------------------------------------
// Device globals (no allocation allowed)
// ---------------------------------------------------------------------------
__device__ __align__(16) __half g_qh[NN * CC];
__device__ __align__(16) __half g_kh[NN * CC];
__device__ float g_pm[NN * NSPLIT];
__device__ float g_ps[NN * NSPLIT];
__device__ float g_pos[NN];

// ---------------------------------------------------------------------------
// PTX helpers (base ISA only: works on compute_103 non-'a')
// ---------------------------------------------------------------------------
__device__ __forceinline__ u32 smem_u32(const void* p) {
    u32 a;
    asm("{ .reg .u64 t; cvta.to.shared.u64 t, %1; cvt.u32.u64 %0, t; }" : "=r"(a) : "l"(p));
    return a;
}
__device__ __forceinline__ void cp_async16(u32 dst, const void* src) {
    asm volatile("cp.async.cg.shared.global [%0], [%1], 16;" :: "r"(dst), "l"(src));
}
__device__ __forceinline__ void cp_commit() {
    asm volatile("cp.async.commit_group;" ::: "memory");
}
__device__ __forceinline__ void cp_wait0() {
    asm volatile("cp.async.wait_group 0;" ::: "memory");
}
__device__ __forceinline__ void ldsm_x4(u32& r0, u32& r1, u32& r2, u32& r3, u32 addr) {
    asm volatile("ldmatrix.sync.aligned.m8n8.x4.shared.b16 {%0,%1,%2,%3}, [%4];"
                 : "=r"(r0), "=r"(r1), "=r"(r2), "=r"(r3) : "r"(addr));
}
__device__ __forceinline__ void mma16816(float& d0, float& d1, float& d2, float& d3,
                                         u32 a0, u32 a1, u32 a2, u32 a3,
                                         u32 b0, u32 b1) {
    asm volatile("mma.sync.aligned.m16n8k16.row.col.f32.f16.f16.f32 "
                 "{%0,%1,%2,%3}, {%4,%5,%6,%7}, {%8,%9}, {%0,%1,%2,%3};"
                 : "+f"(d0), "+f"(d1), "+f"(d2), "+f"(d3)
                 : "r"(a0), "r"(a1), "r"(a2), "r"(a3), "r"(b0), "r"(b1));
}

// ---------------------------------------------------------------------------
// fp32 -> fp16 conversion of q and k
// ---------------------------------------------------------------------------
__global__ void convert_kernel(const float* __restrict__ q, const float* __restrict__ k) {
    const int i = blockIdx.x * blockDim.x + threadIdx.x;   // < NN*CC/4
    float4 a = ((const float4*)q)[i];
    float4 b = ((const float4*)k)[i];
    uint2 oa, ob;
    __half2 h;
    h = __floats2half2_rn(a.x, a.y); oa.x = *(u32*)&h;
    h = __floats2half2_rn(a.z, a.w); oa.y = *(u32*)&h;
    h = __floats2half2_rn(b.x, b.y); ob.x = *(u32*)&h;
    h = __floats2half2_rn(b.z, b.w); ob.y = *(u32*)&h;
    ((uint2*)g_qh)[i] = oa;
    ((uint2*)g_kh)[i] = ob;
}

// ---------------------------------------------------------------------------
// Diagonal: pos[i] = (q_i . k_i)/T in fp32 (exact)
// ---------------------------------------------------------------------------
__global__ void pos_kernel(const float* __restrict__ q, const float* __restrict__ k) {
    const int warp = (blockIdx.x * blockDim.x + threadIdx.x) >> 5;
    const int lane = threadIdx.x & 31;
    if (warp >= NN) return;
    const float4* q4 = (const float4*)(q + (size_t)warp * CC);
    const float4* k4 = (const float4*)(k + (size_t)warp * CC);
    float s = 0.0f;
#pragma unroll
    for (int t = 0; t < 2; t++) {
        const float4 a = q4[lane + 32 * t];
        const float4 b = k4[lane + 32 * t];
        s += a.x * b.x + a.y * b.y + a.z * b.z + a.w * b.w;
    }
#pragma unroll
    for (int off = 16; off; off >>= 1)
        s += __shfl_xor_sync(0xFFFFFFFFu, s, off);
    if (lane == 0) g_pos[warp] = s * INV_T;
}

// ---------------------------------------------------------------------------
// Main: HMMA fp16 GEMM (sim = q k^T / T) fused with online row LSE.
// grid = (NSPLIT, 64), 256 threads (8 warps: 2 m-rows x 4 n-cols of 64x64)
// ---------------------------------------------------------------------------
extern __shared__ char smem[];

__global__ __launch_bounds__(256, 1)
void sim_lse_hmma_kernel() {
    const int tid = threadIdx.x;
    const int wid = tid >> 5;
    const int lane = tid & 31;
    const int warp_m = wid >> 2;            // 0..1
    const int warp_n = wid & 3;             // 0..3
    const int split = blockIdx.x;
    const int rowBase = blockIdx.y * TM;
    const int colBase0 = split * CPS;

    const u32 sbase = smem_u32(smem);

    // ---- load A: q[rowBase..+128, 0..256) fp16 into smem (resident) ----
#pragma unroll
    for (int i = 0; i < 16; i++) {
        const int f = tid + i * 256;        // 0..4095
        const int r = f >> 5;               // row 0..127
        const int g = f & 31;               // 16B seg 0..31
        const uint4 v = *(const uint4*)(g_qh + (size_t)(rowBase + r) * CC + g * 8);
        *(uint4*)(smem + SA + r * A_STRIDE + g * 16) = v;
    }

    // ---- preload B chunk 0 (cols colBase0..+256, k 0..64) via cp.async ----
#pragma unroll
    for (int i = 0; i < 8; i++) {
        const int f = tid + i * 256;        // 0..2047
        const int r = f >> 3;               // col-row 0..255
        const int g = f & 7;
        cp_async16(sbase + SB + r * B_STRIDE + g * 16,
                   g_kh + (size_t)(colBase0 + r) * CC + g * 8);
    }
    cp_commit();
    cp_wait0();
    __syncthreads();

    // accumulators: 4 m-tiles x 8 n-octets x 4 f32
    float acc[4][8][4];
#pragma unroll
    for (int mt = 0; mt < 4; mt++)
#pragma unroll
        for (int no = 0; no < 8; no++)
#pragma unroll
            for (int x = 0; x < 4; x++) acc[mt][no][x] = 0.0f;

    // online LSE state: 8 row-slots per lane (mt x half)
    float rm[8], rs[8];
#pragma unroll
    for (int s = 0; s < 8; s++) { rm[s] = -CUDART_INF_F; rs[s] = 0.0f; }

    // precomputed ldmatrix lane addressing
    const u32 a_lane = (u32)((warp_m * 64 + (lane & 15)) * A_STRIDE + (lane >> 4) * 16);
    const u32 b_lane = (u32)((warp_n * 64 + (lane >> 4) * 8 + (lane & 7)) * B_STRIDE
                             + ((lane >> 3) & 1) * 16);

    for (int t = 0; t < NCHUNKS; t++) {
        const int stage = t & 1;
        const u32 bs = sbase + SB + stage * SB_STAGE;

        // prefetch next chunk into other stage (async, waits at loop end)
        if (t + 1 < NCHUNKS) {
            const int nt = (t + 1) >> 2;
            const int nc = (t + 1) & 3;
            const int colBase = colBase0 + nt * TNT;
            const u32 bd = sbase + SB + ((t + 1) & 1) * SB_STAGE;
#pragma unroll
            for (int i = 0; i < 8; i++) {
                const int f = tid + i * 256;
                const int r = f >> 3;
                const int g = f & 7;
                cp_async16(bd + r * B_STRIDE + g * 16,
                           g_kh + (size_t)(colBase + r) * CC + nc * KCH + g * 8);
            }
            cp_commit();
        }

        // ---- 4 k16 steps over this chunk ----
        const int kc = (t & 3) * KCH;       // A k-offset for this chunk
#pragma unroll
        for (int ks = 0; ks < 4; ks++) {
            u32 a[4][4], b[4][4];
#pragma unroll
            for (int mt = 0; mt < 4; mt++)
                ldsm_x4(a[mt][0], a[mt][1], a[mt][2], a[mt][3],
                        sbase + SA + a_lane + (u32)(mt * 16 * A_STRIDE + (kc + ks * 16) * 2));
#pragma unroll
            for (int nt = 0; nt < 4; nt++)
                ldsm_x4(b[nt][0], b[nt][1], b[nt][2], b[nt][3],
                        bs + b_lane + (u32)(nt * 16 * B_STRIDE + ks * 32));
#pragma unroll
            for (int mt = 0; mt < 4; mt++)
#pragma unroll
                for (int no = 0; no < 8; no++) {
                    const int bt = no >> 1, pr = no & 1;
                    mma16816(acc[mt][no][0], acc[mt][no][1], acc[mt][no][2], acc[mt][no][3],
                             a[mt][0], a[mt][1], a[mt][2], a[mt][3],
                             b[bt][pr * 2], b[bt][pr * 2 + 1]);
                }
        }

        // ---- tile finished: online LSE epilogue, reset accumulators ----
        if ((t & 3) == 3) {
#pragma unroll
            for (int mt = 0; mt < 4; mt++) {
#pragma unroll
                for (int h = 0; h < 2; h++) {
                    const int s = mt * 2 + h;
                    float x[16];
                    float mloc = -CUDART_INF_F;
#pragma unroll
                    for (int no = 0; no < 8; no++) {
                        x[no * 2 + 0] = acc[mt][no][h * 2 + 0] * INV_T;
                        x[no * 2 + 1] = acc[mt][no][h * 2 + 1] * INV_T;
                        mloc = fmaxf(mloc, fmaxf(x[no * 2], x[no * 2 + 1]));
                    }
                    const float mn = fmaxf(rm[s], mloc);
                    float s0 = rs[s] * exp2f((rm[s] - mn) * L2E);
                    float s1 = 0.0f, s2 = 0.0f, s3 = 0.0f;
#pragma unroll
                    for (int j = 0; j < 16; j += 4) {
                        s0 += exp2f((x[j + 0] - mn) * L2E);
                        s1 += exp2f((x[j + 1] - mn) * L2E);
                        s2 += exp2f((x[j + 2] - mn) * L2E);
                        s3 += exp2f((x[j + 3] - mn) * L2E);
                    }
                    rm[s] = mn;
                    rs[s] = (s0 + s1) + (s2 + s3);
                }
#pragma unroll
                for (int no = 0; no < 8; no++)
#pragma unroll
                    for (int xx = 0; xx < 4; xx++) acc[mt][no][xx] = 0.0f;
            }
        }

        cp_wait0();
        __syncthreads();
    }

    // ---- merge across the 4 lanes sharing each row (lane&3 varies cols) ----
#pragma unroll
    for (int s = 0; s < 8; s++) {
#pragma unroll
        for (int off = 1; off <= 2; off <<= 1) {
            const float om = __shfl_xor_sync(0xFFFFFFFFu, rm[s], off);
            const float os = __shfl_xor_sync(0xFFFFFFFFu, rs[s], off);
            const float nm = fmaxf(rm[s], om);
            rs[s] = rs[s] * exp2f((rm[s] - nm) * L2E) + os * exp2f((om - nm) * L2E);
            rm[s] = nm;
        }
    }

    // ---- write per-warp-column partials to smem, reduce, store globals ----
    float* redm = (float*)(smem + SRED_M);
    float* reds = (float*)(smem + SRED_S);
    if ((lane & 3) == 0) {
#pragma unroll
        for (int mt = 0; mt < 4; mt++)
#pragma unroll
            for (int h = 0; h < 2; h++) {
                const int row = warp_m * 64 + mt * 16 + h * 8 + (lane >> 2);
                redm[row * 4 + warp_n] = rm[mt * 2 + h];
                reds[row * 4 + warp_n] = rs[mt * 2 + h];
            }
    }
    __syncthreads();
    if (tid < TM) {
        float mg = -CUDART_INF_F;
#pragma unroll
        for (int w = 0; w < 4; w++) mg = fmaxf(mg, redm[tid * 4 + w]);
        float sg = 0.0f;
#pragma unroll
        for (int w = 0; w < 4; w++)
            sg += reds[tid * 4 + w] * exp2f((redm[tid * 4 + w] - mg) * L2E);
        g_pm[(rowBase + tid) * NSPLIT + split] = mg;
        g_ps[(rowBase + tid) * NSPLIT + split] = sg;
    }
}

// ---------------------------------------------------------------------------
// Combine: merge split partials, mean(lse - pos). Deterministic order.
// ---------------------------------------------------------------------------
__global__ void combine_kernel(float* __restrict__ out) {
    __shared__ float red[256];
    float tot = 0.0f;
    for (int r = threadIdx.x; r < NN; r += 256) {
        const float* pm = g_pm + r * NSPLIT;
        const float* ps = g_ps + r * NSPLIT;
        float mg = fmaxf(pm[0], pm[1]);
        float sg = ps[0] * exp2f((pm[0] - mg) * L2E) + ps[1] * exp2f((pm[1] - mg) * L2E);
        tot += mg + logf(sg) - g_pos[r];
    }
    red[threadIdx.x] = tot;
    __syncthreads();
    for (int o = 128; o; o >>= 1) {
        if (threadIdx.x < o) red[threadIdx.x] += red[threadIdx.x + o];
        __syncthreads();
    }
    if (threadIdx.x == 0) out[0] = red[0] / (float)NN;
}

// ---------------------------------------------------------------------------
extern "C" void kernel_launch(void* const* d_in, const int* in_sizes, int n_in,
                              void* d_out, int out_size) {
    const float* q = (const float*)d_in[0];
    const float* k = (const float*)d_in[1];
    float* out = (float*)d_out;

    cudaFuncSetAttribute(sim_lse_hmma_kernel,
                         cudaFuncAttributeMaxDynamicSharedMemorySize, SM_TOTAL);

    convert_kernel<<<(NN * CC / 4) / 256, 256>>>(q, k);
    pos_kernel<<<NN / 8, 256>>>(q, k);
    dim3 grid(NSPLIT, NN / TM);
    sim_lse_hmma_kernel<<<grid, 256, SM_TOTAL>>>();
    combine_kernel<<<1, 256>>>(out);
}

// round 4
// speedup vs baseline: 5.8440x; 1.0647x over previous
#include <cuda_runtime.h>
#include <cuda_fp16.h>
#include <math_constants.h>

// ---------------------------------------------------------------------------
// Problem constants
// ---------------------------------------------------------------------------
#define NN 8192
#define CC 256
#define TM 128                  // CTA rows
#define TNT 256                 // CTA col-tile width
#define NSPLIT 2
#define CPS (NN / NSPLIT)       // 4096 cols per CTA
#define NTILE (CPS / TNT)       // 16 col tiles
#define KCH 64                  // k per chunk
#define NCHUNKS (NTILE * 4)     // 64 chunk steps
#define INV_T 14.285714285714285714f
#define LN2 0.6931471805599453f
// sqrt(INV_T * log2(e)) — folded into fp16 operands so acc = logit * log2(e)
#define SCALE 4.5398160052f

// SMEM layout (dynamic)
#define A_STRIDE 528            // 256 halves + 8 pad
#define B_STRIDE 144            // 64 halves + 8 pad
#define SA 0
#define SA_BYTES (TM * A_STRIDE)            // 67584
#define SB (SA + SA_BYTES)
#define SB_STAGE (TNT * B_STRIDE)           // 36864
#define SRED_M (SB + 2 * SB_STAGE)          // 141312
#define SRED_S (SRED_M + TM * 4 * 4)
#define SM_TOTAL (SRED_S + TM * 4 * 4)      // 145408

typedef unsigned int u32;

// ---------------------------------------------------------------------------
// Device globals (no allocation allowed)
// ---------------------------------------------------------------------------
__device__ __align__(16) __half g_qh[NN * CC];
__device__ __align__(16) __half g_kh[NN * CC];
__device__ float g_pm[NN * NSPLIT];
__device__ float g_ps[NN * NSPLIT];
__device__ float g_pos[NN];
__device__ float g_part[32];

// ---------------------------------------------------------------------------
// PTX helpers (base ISA only; must compile for compute_103 non-'a')
// ---------------------------------------------------------------------------
__device__ __forceinline__ u32 smem_u32(const void* p) {
    u32 a;
    asm("{ .reg .u64 t; cvta.to.shared.u64 t, %1; cvt.u32.u64 %0, t; }" : "=r"(a) : "l"(p));
    return a;
}
__device__ __forceinline__ void cp_async16(u32 dst, const void* src) {
    asm volatile("cp.async.cg.shared.global [%0], [%1], 16;" :: "r"(dst), "l"(src));
}
__device__ __forceinline__ void cp_commit() {
    asm volatile("cp.async.commit_group;" ::: "memory");
}
__device__ __forceinline__ void cp_wait0() {
    asm volatile("cp.async.wait_group 0;" ::: "memory");
}
__device__ __forceinline__ void ldsm_x4(u32& r0, u32& r1, u32& r2, u32& r3, u32 addr) {
    asm volatile("ldmatrix.sync.aligned.m8n8.x4.shared.b16 {%0,%1,%2,%3}, [%4];"
                 : "=r"(r0), "=r"(r1), "=r"(r2), "=r"(r3) : "r"(addr));
}
__device__ __forceinline__ void mma16816(float& d0, float& d1, float& d2, float& d3,
                                         u32 a0, u32 a1, u32 a2, u32 a3,
                                         u32 b0, u32 b1) {
    asm volatile("mma.sync.aligned.m16n8k16.row.col.f32.f16.f16.f32 "
                 "{%0,%1,%2,%3}, {%4,%5,%6,%7}, {%8,%9}, {%0,%1,%2,%3};"
                 : "+f"(d0), "+f"(d1), "+f"(d2), "+f"(d3)
                 : "r"(a0), "r"(a1), "r"(a2), "r"(a3), "r"(b0), "r"(b1));
}

// ---------------------------------------------------------------------------
// Fused convert (fp32 -> scaled fp16) + diagonal dot. One warp per row.
// ---------------------------------------------------------------------------
__global__ void convert_pos_kernel(const float* __restrict__ q, const float* __restrict__ k) {
    const int row = (blockIdx.x * blockDim.x + threadIdx.x) >> 5;
    const int lane = threadIdx.x & 31;
    const float4* q4 = (const float4*)(q + (size_t)row * CC);
    const float4* k4 = (const float4*)(k + (size_t)row * CC);
    float dot = 0.0f;
#pragma unroll
    for (int t = 0; t < 2; t++) {
        const float4 a = q4[lane + 32 * t];
        const float4 b = k4[lane + 32 * t];
        dot += a.x * b.x + a.y * b.y + a.z * b.z + a.w * b.w;
        uint2 oa, ob;
        __half2 h;
        h = __floats2half2_rn(a.x * SCALE, a.y * SCALE); oa.x = *(u32*)&h;
        h = __floats2half2_rn(a.z * SCALE, a.w * SCALE); oa.y = *(u32*)&h;
        h = __floats2half2_rn(b.x * SCALE, b.y * SCALE); ob.x = *(u32*)&h;
        h = __floats2half2_rn(b.z * SCALE, b.w * SCALE); ob.y = *(u32*)&h;
        ((uint2*)g_qh)[(size_t)row * (CC / 4) + lane + 32 * t] = oa;
        ((uint2*)g_kh)[(size_t)row * (CC / 4) + lane + 32 * t] = ob;
    }
#pragma unroll
    for (int off = 16; off; off >>= 1)
        dot += __shfl_xor_sync(0xFFFFFFFFu, dot, off);
    if (lane == 0) g_pos[row] = dot * INV_T;
}

// ---------------------------------------------------------------------------
// Main: HMMA fp16 GEMM fused with online row LSE (log2 domain).
// grid = (NSPLIT, 64), 256 threads (8 warps: 2 m x 4 n of 64x64)
// ---------------------------------------------------------------------------
extern __shared__ char smem[];

__global__ __launch_bounds__(256, 1)
void sim_lse_hmma_kernel() {
    const int tid = threadIdx.x;
    const int wid = tid >> 5;
    const int lane = tid & 31;
    const int warp_m = wid >> 2;
    const int warp_n = wid & 3;
    const int split = blockIdx.x;
    const int rowBase = blockIdx.y * TM;
    const int colBase0 = split * CPS;

    const u32 sbase = smem_u32(smem);

    // ---- A resident in smem ----
#pragma unroll
    for (int i = 0; i < 16; i++) {
        const int f = tid + i * 256;
        const int r = f >> 5;
        const int g = f & 31;
        const uint4 v = *(const uint4*)(g_qh + (size_t)(rowBase + r) * CC + g * 8);
        *(uint4*)(smem + SA + r * A_STRIDE + g * 16) = v;
    }

    // ---- preload B chunk 0 ----
#pragma unroll
    for (int i = 0; i < 8; i++) {
        const int f = tid + i * 256;
        const int r = f >> 3;
        const int g = f & 7;
        cp_async16(sbase + SB + r * B_STRIDE + g * 16,
                   g_kh + (size_t)(colBase0 + r) * CC + g * 8);
    }
    cp_commit();
    cp_wait0();
    __syncthreads();

    float acc[4][8][4];
#pragma unroll
    for (int mt = 0; mt < 4; mt++)
#pragma unroll
        for (int no = 0; no < 8; no++)
#pragma unroll
            for (int x = 0; x < 4; x++) acc[mt][no][x] = 0.0f;

    float rm[8], rs[8];
#pragma unroll
    for (int s = 0; s < 8; s++) { rm[s] = -CUDART_INF_F; rs[s] = 0.0f; }

    const u32 a_lane = (u32)((warp_m * 64 + (lane & 15)) * A_STRIDE + (lane >> 4) * 16);
    const u32 b_lane = (u32)((warp_n * 64 + (lane >> 4) * 8 + (lane & 7)) * B_STRIDE
                             + ((lane >> 3) & 1) * 16);

    for (int t = 0; t < NCHUNKS; t++) {
        const int stage = t & 1;
        const u32 bs = sbase + SB + stage * SB_STAGE;

        if (t + 1 < NCHUNKS) {
            const int nt = (t + 1) >> 2;
            const int nc = (t + 1) & 3;
            const int colBase = colBase0 + nt * TNT;
            const u32 bd = sbase + SB + ((t + 1) & 1) * SB_STAGE;
#pragma unroll
            for (int i = 0; i < 8; i++) {
                const int f = tid + i * 256;
                const int r = f >> 3;
                const int g = f & 7;
                cp_async16(bd + r * B_STRIDE + g * 16,
                           g_kh + (size_t)(colBase + r) * CC + nc * KCH + g * 8);
            }
            cp_commit();
        }

        const int kc = (t & 3) * KCH;
#pragma unroll
        for (int ks = 0; ks < 4; ks++) {
            u32 a[4][4], b[4][4];
#pragma unroll
            for (int mt = 0; mt < 4; mt++)
                ldsm_x4(a[mt][0], a[mt][1], a[mt][2], a[mt][3],
                        sbase + SA + a_lane + (u32)(mt * 16 * A_STRIDE + (kc + ks * 16) * 2));
#pragma unroll
            for (int nt = 0; nt < 4; nt++)
                ldsm_x4(b[nt][0], b[nt][1], b[nt][2], b[nt][3],
                        bs + b_lane + (u32)(nt * 16 * B_STRIDE + ks * 32));
#pragma unroll
            for (int mt = 0; mt < 4; mt++)
#pragma unroll
                for (int no = 0; no < 8; no++) {
                    const int bt = no >> 1, pr = no & 1;
                    mma16816(acc[mt][no][0], acc[mt][no][1], acc[mt][no][2], acc[mt][no][3],
                             a[mt][0], a[mt][1], a[mt][2], a[mt][3],
                             b[bt][pr * 2], b[bt][pr * 2 + 1]);
                }
        }

        // ---- tile finished: fp16-SIMD online LSE (acc already in log2 units) ----
        if ((t & 3) == 3) {
#pragma unroll
            for (int mt = 0; mt < 4; mt++) {
#pragma unroll
                for (int h = 0; h < 2; h++) {
                    const int s = mt * 2 + h;
                    __half2 x2[8];
#pragma unroll
                    for (int no = 0; no < 8; no++)
                        x2[no] = __floats2half2_rn(acc[mt][no][h * 2 + 0],
                                                   acc[mt][no][h * 2 + 1]);
                    __half2 m2 = __hmax2(x2[0], x2[1]);
                    __half2 m2b = __hmax2(x2[2], x2[3]);
                    __half2 m2c = __hmax2(x2[4], x2[5]);
                    __half2 m2d = __hmax2(x2[6], x2[7]);
                    m2 = __hmax2(__hmax2(m2, m2b), __hmax2(m2c, m2d));
                    const float mloc = __half2float(__hmax(__low2half(m2), __high2half(m2)));
                    const float mn = fmaxf(rm[s], mloc);     // exactly fp16-representable
                    const __half2 mn2 = __float2half2_rn(mn);
                    __half2 s2 = h2exp2(__hsub2(x2[0], mn2));
                    __half2 s2b = h2exp2(__hsub2(x2[1], mn2));
#pragma unroll
                    for (int no = 2; no < 8; no += 2) {
                        s2 = __hadd2(s2, h2exp2(__hsub2(x2[no], mn2)));
                        s2b = __hadd2(s2b, h2exp2(__hsub2(x2[no + 1], mn2)));
                    }
                    s2 = __hadd2(s2, s2b);
                    const float bsm = __half2float(__low2half(s2)) + __half2float(__high2half(s2));
                    rs[s] = rs[s] * exp2f(rm[s] - mn) + bsm;
                    rm[s] = mn;
                }
#pragma unroll
                for (int no = 0; no < 8; no++)
#pragma unroll
                    for (int xx = 0; xx < 4; xx++) acc[mt][no][xx] = 0.0f;
            }
        }

        cp_wait0();
        __syncthreads();
    }

    // ---- merge across the 4 lanes sharing each row ----
#pragma unroll
    for (int s = 0; s < 8; s++) {
#pragma unroll
        for (int off = 1; off <= 2; off <<= 1) {
            const float om = __shfl_xor_sync(0xFFFFFFFFu, rm[s], off);
            const float os = __shfl_xor_sync(0xFFFFFFFFu, rs[s], off);
            const float nm = fmaxf(rm[s], om);
            rs[s] = rs[s] * exp2f(rm[s] - nm) + os * exp2f(om - nm);
            rm[s] = nm;
        }
    }

    // ---- cross-warp reduce + store split partials (log2 domain) ----
    float* redm = (float*)(smem + SRED_M);
    float* reds = (float*)(smem + SRED_S);
    if ((lane & 3) == 0) {
#pragma unroll
        for (int mt = 0; mt < 4; mt++)
#pragma unroll
            for (int h = 0; h < 2; h++) {
                const int row = warp_m * 64 + mt * 16 + h * 8 + (lane >> 2);
                redm[row * 4 + warp_n] = rm[mt * 2 + h];
                reds[row * 4 + warp_n] = rs[mt * 2 + h];
            }
    }
    __syncthreads();
    if (tid < TM) {
        float mg = -CUDART_INF_F;
#pragma unroll
        for (int w = 0; w < 4; w++) mg = fmaxf(mg, redm[tid * 4 + w]);
        float sg = 0.0f;
#pragma unroll
        for (int w = 0; w < 4; w++)
            sg += reds[tid * 4 + w] * exp2f(redm[tid * 4 + w] - mg);
        g_pm[(rowBase + tid) * NSPLIT + split] = mg;
        g_ps[(rowBase + tid) * NSPLIT + split] = sg;
    }
}

// ---------------------------------------------------------------------------
// Combine stage 1: 32 blocks x 256 rows -> per-block partial sums
// ---------------------------------------------------------------------------
__global__ void combine1_kernel() {
    __shared__ float red[256];
    const int r = blockIdx.x * 256 + threadIdx.x;
    const float* pm = g_pm + r * NSPLIT;
    const float* ps = g_ps + r * NSPLIT;
    const float mg = fmaxf(pm[0], pm[1]);
    const float sg = ps[0] * exp2f(pm[0] - mg) + ps[1] * exp2f(pm[1] - mg);
    red[threadIdx.x] = LN2 * (mg + log2f(sg)) - g_pos[r];
    __syncthreads();
    for (int o = 128; o; o >>= 1) {
        if (threadIdx.x < o) red[threadIdx.x] += red[threadIdx.x + o];
        __syncthreads();
    }
    if (threadIdx.x == 0) g_part[blockIdx.x] = red[0];
}

// Combine stage 2: fixed-order sum of the 32 partials (deterministic)
__global__ void combine2_kernel(float* __restrict__ out) {
    if (threadIdx.x == 0) {
        float t = 0.0f;
#pragma unroll
        for (int i = 0; i < 32; i++) t += g_part[i];
        out[0] = t / (float)NN;
    }
}

// ---------------------------------------------------------------------------
extern "C" void kernel_launch(void* const* d_in, const int* in_sizes, int n_in,
                              void* d_out, int out_size) {
    const float* q = (const float*)d_in[0];
    const float* k = (const float*)d_in[1];
    float* out = (float*)d_out;

    cudaFuncSetAttribute(sim_lse_hmma_kernel,
                         cudaFuncAttributeMaxDynamicSharedMemorySize, SM_TOTAL);

    convert_pos_kernel<<<NN * 32 / 256, 256>>>(q, k);
    dim3 grid(NSPLIT, NN / TM);
    sim_lse_hmma_kernel<<<grid, 256, SM_TOTAL>>>();
    combine1_kernel<<<32, 256>>>();
    combine2_kernel<<<1, 32>>>(out);
}

// round 5
// speedup vs baseline: 6.5681x; 1.1239x over previous
#include <cuda_runtime.h>
#include <cuda_fp16.h>
#include <math_constants.h>

// ---------------------------------------------------------------------------
// Problem constants
// ---------------------------------------------------------------------------
#define NN 8192
#define CC 256
#define TM 128                  // CTA rows
#define TNT 128                 // CTA col-tile width
#define NSPLIT 4
#define CPS (NN / NSPLIT)       // 2048 cols per CTA
#define NTILE (CPS / TNT)       // 16 col tiles
#define KCH 64                  // k per chunk
#define NCHUNKS (NTILE * 4)     // 64 chunk steps
#define INV_T 14.285714285714285714f
#define LN2 0.6931471805599453f
// sqrt(INV_T * log2(e)) folded into fp16 operands: acc = logit * log2(e)
#define SCALE 4.5398160052f

// SMEM layout (dynamic)
#define A_STRIDE 528            // 256 halves + 8 pad
#define B_STRIDE 144            // 64 halves + 8 pad
#define SA 0
#define SA_BYTES (TM * A_STRIDE)            // 67584
#define SB (SA + SA_BYTES)
#define SB_STAGE (TNT * B_STRIDE)           // 18432
#define SRED_M (SB + 2 * SB_STAGE)          // 104448
#define SRED_S (SRED_M + TM * 2 * 4)        // +1024
#define SM_TOTAL (SRED_S + TM * 2 * 4)      // 106496  (x2 CTAs = 212992 < 228KB)

typedef unsigned int u32;

// ---------------------------------------------------------------------------
// Device globals (no allocation allowed)
// ---------------------------------------------------------------------------
__device__ __align__(16) __half g_qh[NN * CC];
__device__ __align__(16) __half g_kh[NN * CC];
__device__ float g_pm[NN * NSPLIT];
__device__ float g_ps[NN * NSPLIT];
__device__ float g_pos[NN];
__device__ float g_part[32];
__device__ unsigned int g_ticket;   // zero-initialized; reset by last block

// ---------------------------------------------------------------------------
// PTX helpers (base ISA only; must compile for compute_103 non-'a')
// ---------------------------------------------------------------------------
__device__ __forceinline__ u32 smem_u32(const void* p) {
    u32 a;
    asm("{ .reg .u64 t; cvta.to.shared.u64 t, %1; cvt.u32.u64 %0, t; }" : "=r"(a) : "l"(p));
    return a;
}
__device__ __forceinline__ void cp_async16(u32 dst, const void* src) {
    asm volatile("cp.async.cg.shared.global [%0], [%1], 16;" :: "r"(dst), "l"(src));
}
__device__ __forceinline__ void cp_commit() {
    asm volatile("cp.async.commit_group;" ::: "memory");
}
__device__ __forceinline__ void cp_wait0() {
    asm volatile("cp.async.wait_group 0;" ::: "memory");
}
__device__ __forceinline__ void ldsm_x4(u32& r0, u32& r1, u32& r2, u32& r3, u32 addr) {
    asm volatile("ldmatrix.sync.aligned.m8n8.x4.shared.b16 {%0,%1,%2,%3}, [%4];"
                 : "=r"(r0), "=r"(r1), "=r"(r2), "=r"(r3) : "r"(addr));
}
__device__ __forceinline__ void mma16816(float& d0, float& d1, float& d2, float& d3,
                                         u32 a0, u32 a1, u32 a2, u32 a3,
                                         u32 b0, u32 b1) {
    asm volatile("mma.sync.aligned.m16n8k16.row.col.f32.f16.f16.f32 "
                 "{%0,%1,%2,%3}, {%4,%5,%6,%7}, {%8,%9}, {%0,%1,%2,%3};"
                 : "+f"(d0), "+f"(d1), "+f"(d2), "+f"(d3)
                 : "r"(a0), "r"(a1), "r"(a2), "r"(a3), "r"(b0), "r"(b1));
}

// ---------------------------------------------------------------------------
// Fused convert (fp32 -> scaled fp16) + diagonal dot. One warp per row.
// ---------------------------------------------------------------------------
__global__ void convert_pos_kernel(const float* __restrict__ q, const float* __restrict__ k) {
    const int row = (blockIdx.x * blockDim.x + threadIdx.x) >> 5;
    const int lane = threadIdx.x & 31;
    const float4* q4 = (const float4*)(q + (size_t)row * CC);
    const float4* k4 = (const float4*)(k + (size_t)row * CC);
    float dot = 0.0f;
#pragma unroll
    for (int t = 0; t < 2; t++) {
        const float4 a = q4[lane + 32 * t];
        const float4 b = k4[lane + 32 * t];
        dot += a.x * b.x + a.y * b.y + a.z * b.z + a.w * b.w;
        uint2 oa, ob;
        __half2 h;
        h = __floats2half2_rn(a.x * SCALE, a.y * SCALE); oa.x = *(u32*)&h;
        h = __floats2half2_rn(a.z * SCALE, a.w * SCALE); oa.y = *(u32*)&h;
        h = __floats2half2_rn(b.x * SCALE, b.y * SCALE); ob.x = *(u32*)&h;
        h = __floats2half2_rn(b.z * SCALE, b.w * SCALE); ob.y = *(u32*)&h;
        ((uint2*)g_qh)[(size_t)row * (CC / 4) + lane + 32 * t] = oa;
        ((uint2*)g_kh)[(size_t)row * (CC / 4) + lane + 32 * t] = ob;
    }
#pragma unroll
    for (int off = 16; off; off >>= 1)
        dot += __shfl_xor_sync(0xFFFFFFFFu, dot, off);
    if (lane == 0) g_pos[row] = dot * INV_T;
}

// ---------------------------------------------------------------------------
// Main: HMMA fp16 GEMM fused with online row LSE (log2 domain).
// grid = (NSPLIT=4, 64) = 256 CTAs, 256 threads, 2 CTAs/SM.
// 8 warps: 4 m-groups x 2 n-groups, warp tile 32x64.
// ---------------------------------------------------------------------------
extern __shared__ char smem[];

__global__ __launch_bounds__(256, 2)
void sim_lse_hmma_kernel() {
    const int tid = threadIdx.x;
    const int wid = tid >> 5;
    const int lane = tid & 31;
    const int warp_m = wid >> 1;            // 0..3 (32 rows each)
    const int warp_n = wid & 1;             // 0..1 (64 cols each)
    const int split = blockIdx.x;
    const int rowBase = blockIdx.y * TM;
    const int colBase0 = split * CPS;

    const u32 sbase = smem_u32(smem);

    // ---- A resident in smem ----
#pragma unroll
    for (int i = 0; i < 16; i++) {
        const int f = tid + i * 256;
        const int r = f >> 5;
        const int g = f & 31;
        const uint4 v = *(const uint4*)(g_qh + (size_t)(rowBase + r) * CC + g * 8);
        *(uint4*)(smem + SA + r * A_STRIDE + g * 16) = v;
    }

    // ---- preload B chunk 0 (128 cols x 64 k) ----
#pragma unroll
    for (int i = 0; i < 4; i++) {
        const int f = tid + i * 256;        // 0..1023
        const int r = f >> 3;               // col 0..127
        const int g = f & 7;
        cp_async16(sbase + SB + r * B_STRIDE + g * 16,
                   g_kh + (size_t)(colBase0 + r) * CC + g * 8);
    }
    cp_commit();
    cp_wait0();
    __syncthreads();

    float acc[2][8][4];
#pragma unroll
    for (int mt = 0; mt < 2; mt++)
#pragma unroll
        for (int no = 0; no < 8; no++)
#pragma unroll
            for (int x = 0; x < 4; x++) acc[mt][no][x] = 0.0f;

    float rm[4], rs[4];
#pragma unroll
    for (int s = 0; s < 4; s++) { rm[s] = -CUDART_INF_F; rs[s] = 0.0f; }

    const u32 a_lane = (u32)((warp_m * 32 + (lane & 15)) * A_STRIDE + (lane >> 4) * 16);
    const u32 b_lane = (u32)((warp_n * 64 + (lane >> 4) * 8 + (lane & 7)) * B_STRIDE
                             + ((lane >> 3) & 1) * 16);

    for (int t = 0; t < NCHUNKS; t++) {
        const u32 bs = sbase + SB + (t & 1) * SB_STAGE;

        if (t + 1 < NCHUNKS) {
            const int nt = (t + 1) >> 2;
            const int nc = (t + 1) & 3;
            const int colBase = colBase0 + nt * TNT;
            const u32 bd = sbase + SB + ((t + 1) & 1) * SB_STAGE;
#pragma unroll
            for (int i = 0; i < 4; i++) {
                const int f = tid + i * 256;
                const int r = f >> 3;
                const int g = f & 7;
                cp_async16(bd + r * B_STRIDE + g * 16,
                           g_kh + (size_t)(colBase + r) * CC + nc * KCH + g * 8);
            }
            cp_commit();
        }

        const int kc = (t & 3) * KCH;
#pragma unroll
        for (int ks = 0; ks < 4; ks++) {
            u32 a[2][4], b[4][4];
#pragma unroll
            for (int mt = 0; mt < 2; mt++)
                ldsm_x4(a[mt][0], a[mt][1], a[mt][2], a[mt][3],
                        sbase + SA + a_lane + (u32)(mt * 16 * A_STRIDE + (kc + ks * 16) * 2));
#pragma unroll
            for (int nt = 0; nt < 4; nt++)
                ldsm_x4(b[nt][0], b[nt][1], b[nt][2], b[nt][3],
                        bs + b_lane + (u32)(nt * 16 * B_STRIDE + ks * 32));
#pragma unroll
            for (int mt = 0; mt < 2; mt++)
#pragma unroll
                for (int no = 0; no < 8; no++) {
                    const int bt = no >> 1, pr = no & 1;
                    mma16816(acc[mt][no][0], acc[mt][no][1], acc[mt][no][2], acc[mt][no][3],
                             a[mt][0], a[mt][1], a[mt][2], a[mt][3],
                             b[bt][pr * 2], b[bt][pr * 2 + 1]);
                }
        }

        // ---- tile finished: fp16-SIMD online LSE (acc in log2 units) ----
        if ((t & 3) == 3) {
#pragma unroll
            for (int mt = 0; mt < 2; mt++) {
#pragma unroll
                for (int h = 0; h < 2; h++) {
                    const int s = mt * 2 + h;
                    __half2 x2[8];
#pragma unroll
                    for (int no = 0; no < 8; no++)
                        x2[no] = __floats2half2_rn(acc[mt][no][h * 2 + 0],
                                                   acc[mt][no][h * 2 + 1]);
                    __half2 m2 = __hmax2(__hmax2(__hmax2(x2[0], x2[1]), __hmax2(x2[2], x2[3])),
                                         __hmax2(__hmax2(x2[4], x2[5]), __hmax2(x2[6], x2[7])));
                    const float mloc = __half2float(__hmax(__low2half(m2), __high2half(m2)));
                    const float mn = fmaxf(rm[s], mloc);     // exactly fp16-representable
                    const __half2 mn2 = __float2half2_rn(mn);
                    __half2 s2 = h2exp2(__hsub2(x2[0], mn2));
                    __half2 s2b = h2exp2(__hsub2(x2[1], mn2));
#pragma unroll
                    for (int no = 2; no < 8; no += 2) {
                        s2 = __hadd2(s2, h2exp2(__hsub2(x2[no], mn2)));
                        s2b = __hadd2(s2b, h2exp2(__hsub2(x2[no + 1], mn2)));
                    }
                    s2 = __hadd2(s2, s2b);
                    const float bsm = __half2float(__low2half(s2)) + __half2float(__high2half(s2));
                    rs[s] = rs[s] * exp2f(rm[s] - mn) + bsm;
                    rm[s] = mn;
                }
#pragma unroll
                for (int no = 0; no < 8; no++)
#pragma unroll
                    for (int xx = 0; xx < 4; xx++) acc[mt][no][xx] = 0.0f;
            }
        }

        cp_wait0();
        __syncthreads();
    }

    // ---- merge across the 4 lanes sharing each row ----
#pragma unroll
    for (int s = 0; s < 4; s++) {
#pragma unroll
        for (int off = 1; off <= 2; off <<= 1) {
            const float om = __shfl_xor_sync(0xFFFFFFFFu, rm[s], off);
            const float os = __shfl_xor_sync(0xFFFFFFFFu, rs[s], off);
            const float nm = fmaxf(rm[s], om);
            rs[s] = rs[s] * exp2f(rm[s] - nm) + os * exp2f(om - nm);
            rm[s] = nm;
        }
    }

    // ---- cross-warp reduce (2 warp_n groups) + store split partials ----
    float* redm = (float*)(smem + SRED_M);
    float* reds = (float*)(smem + SRED_S);
    if ((lane & 3) == 0) {
#pragma unroll
        for (int mt = 0; mt < 2; mt++)
#pragma unroll
            for (int h = 0; h < 2; h++) {
                const int row = warp_m * 32 + mt * 16 + h * 8 + (lane >> 2);
                redm[row * 2 + warp_n] = rm[mt * 2 + h];
                reds[row * 2 + warp_n] = rs[mt * 2 + h];
            }
    }
    __syncthreads();
    if (tid < TM) {
        const float m0 = redm[tid * 2], m1 = redm[tid * 2 + 1];
        const float mg = fmaxf(m0, m1);
        const float sg = reds[tid * 2] * exp2f(m0 - mg) + reds[tid * 2 + 1] * exp2f(m1 - mg);
        g_pm[(rowBase + tid) * NSPLIT + split] = mg;
        g_ps[(rowBase + tid) * NSPLIT + split] = sg;
    }
}

// ---------------------------------------------------------------------------
// Combine (single launch): 32 blocks reduce 256 rows each; the last block to
// finish sums the 32 partials in fixed order (deterministic) and writes out.
// ---------------------------------------------------------------------------
__global__ void combine_kernel(float* __restrict__ out) {
    __shared__ float red[256];
    __shared__ bool amLast;
    const int r = blockIdx.x * 256 + threadIdx.x;
    const float4 pm = *(const float4*)(g_pm + r * NSPLIT);
    const float4 ps = *(const float4*)(g_ps + r * NSPLIT);
    const float mg = fmaxf(fmaxf(pm.x, pm.y), fmaxf(pm.z, pm.w));
    const float sg = ps.x * exp2f(pm.x - mg) + ps.y * exp2f(pm.y - mg)
                   + ps.z * exp2f(pm.z - mg) + ps.w * exp2f(pm.w - mg);
    red[threadIdx.x] = LN2 * (mg + log2f(sg)) - g_pos[r];
    __syncthreads();
    for (int o = 128; o; o >>= 1) {
        if (threadIdx.x < o) red[threadIdx.x] += red[threadIdx.x + o];
        __syncthreads();
    }
    if (threadIdx.x == 0) {
        g_part[blockIdx.x] = red[0];
        __threadfence();
        const unsigned int t = atomicAdd(&g_ticket, 1u);
        amLast = (t == 31u);
    }
    __syncthreads();
    if (amLast && threadIdx.x == 0) {
        float tot = 0.0f;
#pragma unroll
        for (int i = 0; i < 32; i++) tot += g_part[i];
        out[0] = tot / (float)NN;
        g_ticket = 0u;   // reset for next graph replay
    }
}

// ---------------------------------------------------------------------------
extern "C" void kernel_launch(void* const* d_in, const int* in_sizes, int n_in,
                              void* d_out, int out_size) {
    const float* q = (const float*)d_in[0];
    const float* k = (const float*)d_in[1];
    float* out = (float*)d_out;

    cudaFuncSetAttribute(sim_lse_hmma_kernel,
                         cudaFuncAttributeMaxDynamicSharedMemorySize, SM_TOTAL);

    convert_pos_kernel<<<NN * 32 / 256, 256>>>(q, k);
    dim3 grid(NSPLIT, NN / TM);
    sim_lse_hmma_kernel<<<grid, 256, SM_TOTAL>>>();
    combine_kernel<<<32, 256>>>(out);
}